// round 5
// baseline (speedup 1.0000x reference)
#include <cuda_runtime.h>

// FlowNet2 Resample2d (kernel_size=1) bilinear warp.
// input1: [B, C, H, W] float, input2 (flow): [B, 2, H, W] float
//
// R2's scalar-gather structure (vector-load variants proven 2-4x worse:
// scattered wide loads pay the unique-sector cost once per 4B slice).
// New in R5: block = one full output row (512 threads), channel loop in
// lockstep via __syncthreads every 4 channels. Per-channel input tile
// (~5 rows x 512 x 4B ~ 10KB) x 4 blocks/SM stays resident in the 228KB L1,
// converting the gather stream from L2-served (57% LTS in R2) to L1 hits.

#define BB 8
#define CC 32
#define HH 512
#define WW 512
#define HWSZ (HH * WW)   // 2^18

__global__ __launch_bounds__(512, 4)
void resample2d_kernel(const float* __restrict__ in1,
                       const float* __restrict__ flow,
                       float* __restrict__ out) {
    int bh = blockIdx.x;           // [0, B*H)
    int b  = bh >> 9;              // / HH
    int h  = bh & (HH - 1);
    int w  = threadIdx.x;          // [0, 512)
    int hw = (h << 9) | w;

    const float* fl = flow + ((size_t)b << 19); // b * 2 * HWSZ
    float dx = __ldg(fl + hw);
    float dy = __ldg(fl + HWSZ + hw);

    float xf = (float)w + dx;
    float yf = (float)h + dy;
    float x0 = floorf(xf);
    float y0 = floorf(yf);
    float alpha = xf - x0;   // unclamped fractional weights
    float beta  = yf - y0;

    int ix0 = (int)x0;
    int iy0 = (int)y0;
    int xL = min(max(ix0,     0), WW - 1);
    int xR = min(max(ix0 + 1, 0), WW - 1);
    int yT = min(max(iy0,     0), HH - 1);
    int yB = min(max(iy0 + 1, 0), HH - 1);

    float wTR = alpha * (1.0f - beta);
    float wBL = (1.0f - alpha) * beta;
    float wBR = alpha * beta;
    float wTL = 1.0f - wTR - wBL - wBR;

    int iTL = (yT << 9) + xL;
    int iTR = (yT << 9) + xR;
    int iBL = (yB << 9) + xL;
    int iBR = (yB << 9) + xR;

    const float* base = in1 + ((size_t)b << 23);   // b * C * HWSZ
    float* op = out + ((size_t)b << 23) + hw;

    for (int c0 = 0; c0 < CC; c0 += 4) {
        #pragma unroll
        for (int u = 0; u < 4; u++) {
            int off = (c0 + u) << 18;   // c * HWSZ
            const float* p = base + off;
            float v = wTL * __ldg(p + iTL)
                    + wTR * __ldg(p + iTR)
                    + wBL * __ldg(p + iBL)
                    + wBR * __ldg(p + iBR);
            op[off] = v;
        }
        // Keep all 16 warps of the block on the same channel group so the
        // per-channel tile stays hot in L1 (uniform control flow: safe).
        __syncthreads();
    }
}

extern "C" void kernel_launch(void* const* d_in, const int* in_sizes, int n_in,
                              void* d_out, int out_size) {
    const float* input1 = (const float*)d_in[0];
    const float* input2 = (const float*)d_in[1];
    float* out = (float*)d_out;

    const int blocks = BB * HH;    // 4096 blocks, one output row each
    resample2d_kernel<<<blocks, 512>>>(input1, input2, out);
}

// round 6
// speedup vs baseline: 1.3978x; 1.3978x over previous
#include <cuda_runtime.h>

// FlowNet2 Resample2d (kernel_size=1) bilinear warp.
// input1: [B, C, H, W] float, input2 (flow): [B, 2, H, W] float
//
// R2's scalar-gather structure (proven best: vector loads on scattered
// gathers pay per-4B-slice; barriers stall). New: 2D block geometry —
// each 256-thread block covers a 64-wide x 4-tall pixel tile, so warps
// handling vertically adjacent rows are co-resident on one SM. Their
// gather windows overlap 7/8 in y, converting the TL/BL compulsory L1
// misses (previously refilled from L2, ~600MB measured in R2) into L1
// hits and removing the miss-replay wavefronts.

#define BB 8
#define CC 32
#define HH 512
#define WW 512
#define HWSZ (HH * WW)   // 2^18

__global__ __launch_bounds__(256, 8)
void resample2d_kernel(const float* __restrict__ in1,
                       const float* __restrict__ flow,
                       float* __restrict__ out) {
    // Block tile: 64 px wide x 4 rows. Grid = 8 x-chunks * 128 y-chunks * 8 batches.
    int blk = blockIdx.x;
    int x0 = (blk & 7) << 6;            // x-chunk * 64
    int y0 = ((blk >> 3) & 127) << 2;   // y-chunk * 4
    int b  = blk >> 10;                 // batch

    int w = x0 + (threadIdx.x & 63);
    int h = y0 + (threadIdx.x >> 6);
    int hw = (h << 9) | w;

    const float* fl = flow + ((size_t)b << 19); // b * 2 * HWSZ
    float dx = __ldg(fl + hw);
    float dy = __ldg(fl + HWSZ + hw);

    float xf = (float)w + dx;
    float yf = (float)h + dy;
    float x0f = floorf(xf);
    float y0f = floorf(yf);
    float alpha = xf - x0f;   // unclamped fractional weights
    float beta  = yf - y0f;

    int ix0 = (int)x0f;
    int iy0 = (int)y0f;
    int xL = min(max(ix0,     0), WW - 1);
    int xR = min(max(ix0 + 1, 0), WW - 1);
    int yT = min(max(iy0,     0), HH - 1);
    int yB = min(max(iy0 + 1, 0), HH - 1);

    float wTR = alpha * (1.0f - beta);
    float wBL = (1.0f - alpha) * beta;
    float wBR = alpha * beta;
    float wTL = 1.0f - wTR - wBL - wBR;

    const float* base = in1 + ((size_t)b << 23);   // b * C * HWSZ
    const float* pTL = base + ((yT << 9) + xL);
    const float* pTR = base + ((yT << 9) + xR);
    const float* pBL = base + ((yB << 9) + xL);
    const float* pBR = base + ((yB << 9) + xR);
    float* op = out + ((size_t)b << 23) + hw;

    #pragma unroll 4
    for (int c = 0; c < CC; c++) {
        int off = c << 18;   // c * HWSZ
        float v = wTL * __ldg(pTL + off)
                + wTR * __ldg(pTR + off)
                + wBL * __ldg(pBL + off)
                + wBR * __ldg(pBR + off);
        op[off] = v;
    }
}

extern "C" void kernel_launch(void* const* d_in, const int* in_sizes, int n_in,
                              void* d_out, int out_size) {
    const float* input1 = (const float*)d_in[0];
    const float* input2 = (const float*)d_in[1];
    float* out = (float*)d_out;

    const int blocks = 8 * 128 * BB;   // 8192: 8 x-chunks * 128 y-chunks * 8 batches
    resample2d_kernel<<<blocks, 256>>>(input1, input2, out);
}